// round 5
// baseline (speedup 1.0000x reference)
#include <cuda_runtime.h>
#include <math.h>

#define HIDDEN   1024
#define NROW_MAX 8192
#define TILE     16
#define HSTRIDE  1026    // even, ==2 mod 32: conflict-free pass-B, 8B-aligned rows

// scratch (static device arrays; no allocation)
__device__ int   g_code [NROW_MAX * 32];
__device__ float g_score[NROW_MAX * 32];

typedef unsigned long long ull;

__device__ __forceinline__ ull pack2(float lo, float hi) {
    ull r; asm("mov.b64 %0, {%1, %2};" : "=l"(r) : "f"(lo), "f"(hi)); return r;
}
__device__ __forceinline__ void fma2(ull& d, ull a, ull b, ull c) {
    asm("fma.rn.f32x2 %0, %1, %2, %3;" : "=l"(d) : "l"(a), "l"(b), "l"(c));
}
__device__ __forceinline__ void unpack2(ull v, float& lo, float& hi) {
    asm("mov.b64 {%0, %1}, %2;" : "=f"(lo), "=f"(hi) : "l"(v));
}

template<int N, int H>
__device__ __forceinline__ void fwht_stage(float* v) {
#pragma unroll
    for (int q = 0; q < N; q += 2 * H)
#pragma unroll
        for (int p = 0; p < H; ++p) {
            float a = v[q + p], b = v[q + H + p];
            v[q + p] = a + b; v[q + H + p] = a - b;
        }
}
__device__ __forceinline__ void fwht16(float* v) {
    fwht_stage<16,1>(v); fwht_stage<16,2>(v); fwht_stage<16,4>(v); fwht_stage<16,8>(v);
}
__device__ __forceinline__ void fwht32(float* v) {
    fwht_stage<32,1>(v); fwht_stage<32,2>(v); fwht_stage<32,4>(v);
    fwht_stage<32,8>(v); fwht_stage<32,16>(v);
}

// ---------------------------------------------------------------------------
// Phase 1: LN + BH4 (4 stages) + code/score.
// CTA: 16 rows, 256 threads (8 warps), 3 CTAs/SM (66 KB smem, no sW).
// W is read DIRECTLY from global (L2-resident, warp-broadcast LDG.128):
//   no staging, no intra-stage barriers. Warp w owns blocks {q*8+w} and all
//   16 rows exclusively -> matmul + fused FWHT pass A is barrier-free.
// ---------------------------------------------------------------------------
extern __shared__ float smem[];

__global__ __launch_bounds__(256, 3)
void phase1_kernel(const float* __restrict__ x,
                   const float* __restrict__ gamma,
                   const float* __restrict__ beta,
                   const float* __restrict__ W,     // [4][32][32][32]
                   const float* __restrict__ bias)  // [320]
{
    float* sH  = smem;                     // 16 * 1026
    float* sMu = sH + TILE * HSTRIDE;      // 16
    float* sRs = sMu + 16;                 // 16

    const int tid  = threadIdx.x;
    const int w    = tid >> 5;
    const int lane = tid & 31;
    const int row0 = blockIdx.x * TILE;

    // ---------------- LayerNorm: each warp handles 2 rows ----------------
#pragma unroll
    for (int it = 0; it < 2; ++it) {
        const int r = w * 2 + it;
        const float4* xr = (const float4*)(x + (size_t)(row0 + r) * HIDDEN);
        float4 v[8];
        float s = 0.f, ss = 0.f;
#pragma unroll
        for (int c = 0; c < 8; ++c) {
            v[c] = xr[c * 32 + lane];
            s  += v[c].x + v[c].y + v[c].z + v[c].w;
            ss += v[c].x * v[c].x + v[c].y * v[c].y + v[c].z * v[c].z + v[c].w * v[c].w;
        }
#pragma unroll
        for (int o = 16; o; o >>= 1) {
            s  += __shfl_xor_sync(0xffffffffu, s,  o);
            ss += __shfl_xor_sync(0xffffffffu, ss, o);
        }
        const float mu  = s * (1.f / 1024.f);
        const float var = ss * (1.f / 1024.f) - mu * mu;
        const float rs  = rsqrtf(var + 1e-12f);
        if (lane == 0) { sMu[r] = mu; sRs[r] = rs; }
        float* hr = sH + r * HSTRIDE;
#pragma unroll
        for (int c = 0; c < 8; ++c) {
            const int k = c * 128 + lane * 4;
            const float4 gm = ((const float4*)gamma)[c * 32 + lane];
            const float4 bt = ((const float4*)beta )[c * 32 + lane];
            hr[k + 0] = (v[c].x - mu) * rs * gm.x + bt.x;
            hr[k + 1] = (v[c].y - mu) * rs * gm.y + bt.y;
            hr[k + 2] = (v[c].z - mu) * rs * gm.z + bt.z;
            hr[k + 3] = (v[c].w - mu) * rs * gm.w + bt.w;
        }
    }

    const int row = lane & 15;
    const int jq  = lane >> 4;

    // ---------------- 4 BH4 stages: 2 barriers per stage ----------------
    for (int s = 0; s < 4; ++s) {
        __syncthreads();   // sH ready (LN or previous pass B)

#pragma unroll
        for (int q = 0; q < 4; ++q) {
            const int blk = q * 8 + w;
            float* hrow = sH + row * HSTRIDE + blk * 32;
            const ulonglong2* __restrict__ wg =
                (const ulonglong2*)(W + ((size_t)s * 32 + blk) * 1024 + jq * 16);

            ull acc2[8];
#pragma unroll
            for (int k = 0; k < 8; ++k) acc2[k] = 0ull;

#pragma unroll
            for (int i = 0; i < 32; ++i) {
                const float h = hrow[i];          // 16-lane LDS broadcast
                const ull hh = pack2(h, h);
                ulonglong2 wa = wg[i * 8 + 0];    // LDG.128, warp-broadcast, L2-resident
                ulonglong2 wb = wg[i * 8 + 1];
                fma2(acc2[0], hh, wa.x, acc2[0]); fma2(acc2[1], hh, wa.y, acc2[1]);
                fma2(acc2[2], hh, wb.x, acc2[2]); fma2(acc2[3], hh, wb.y, acc2[3]);
                wa = wg[i * 8 + 2]; wb = wg[i * 8 + 3];
                fma2(acc2[4], hh, wa.x, acc2[4]); fma2(acc2[5], hh, wa.y, acc2[5]);
                fma2(acc2[6], hh, wb.x, acc2[6]); fma2(acc2[7], hh, wb.y, acc2[7]);
            }

            // fused FWHT pass A: fwht16 on this half, then cross-half butterfly
            float va[16];
#pragma unroll
            for (int k = 0; k < 8; ++k) unpack2(acc2[k], va[2 * k], va[2 * k + 1]);
            fwht16(va);
#pragma unroll
            for (int k = 0; k < 16; ++k) {
                const float o = __shfl_xor_sync(0xffffffffu, va[k], 16);
                va[k] = (jq == 0) ? (va[k] + o) : (o - va[k]);
            }
#pragma unroll
            for (int k = 0; k < 16; ++k) hrow[jq * 16 + k] = va[k];
        }
        __syncthreads();   // all pass-A writes visible

        // FWHT pass B: across 32-blocks (stride 32), conflict-free w/ HSTRIDE=1026
#pragma unroll
        for (int g = 0; g < 2; ++g) {
            const int id = tid + g * 256;
            float* p = sH + (id & 15) * HSTRIDE + (id >> 4);
            float vv[32];
#pragma unroll
            for (int c = 0; c < 32; ++c) vv[c] = p[c * 32];
            fwht32(vv);
#pragma unroll
            for (int c = 0; c < 32; ++c) p[c * 32] = vv[c];
        }
    }
    __syncthreads();

    // ---------------- z -> code, score (xn recomputed from x, mu, rs) -------
#pragma unroll
    for (int g = 0; g < 2; ++g) {
        const int id = tid + g * 256;
        const int r  = id & 15;
        const int t  = id >> 4;
        const int n  = row0 + r;
        const float mu = sMu[r], rs = sRs[r];
        const float* xrow = x + (size_t)n * HIDDEN;
        int code = 0;
        float sc = 1.f;
#pragma unroll
        for (int j = 0; j < 10; ++j) {
            const int k = t * 10 + j;
            const float xn = (xrow[k] - mu) * rs * gamma[k] + beta[k];
            const float z  = 0.7f * sH[r * HSTRIDE + k] + 0.3f * xn + bias[k];
            if (z > 0.f) code |= (1 << j);
            sc *= 1.f / (1.f + __expf(-fabsf(z)));
        }
        g_code [n * 32 + t] = t * 1024 + code;   // pre-offset into flat table
        g_score[n * 32 + t] = sc;
    }
}

// ---------------------------------------------------------------------------
// Phase 2: out[n] = sum_t score[n,t] * tables_flat[code[n,t]] + out_bias
// 8 rows per CTA (grid = nrows/8), register accumulators, table loop
// OUTERMOST so concurrent CTAs sweep the same L2-resident table segment.
// ~80 regs -> 3 CTAs/SM -> occupancy ~3x vs R4.
// ---------------------------------------------------------------------------
__global__ __launch_bounds__(256, 3)
void phase2_kernel(const float* __restrict__ tables,
                   const float* __restrict__ obias,
                   float* __restrict__ out)
{
    __shared__ float sc[32][8];
    __shared__ int   cd[32][8];
    const int n0  = blockIdx.x * 8;
    const int tid = threadIdx.x;

    {
        const int r = tid & 7;
        const int t = tid >> 3;
        sc[t][r] = g_score[(n0 + r) * 32 + t];
        cd[t][r] = g_code [(n0 + r) * 32 + t];
    }
    __syncthreads();

    const float4 ob = ((const float4*)obias)[tid];
    float4 a[8];
#pragma unroll
    for (int r = 0; r < 8; ++r) a[r] = ob;

    const float4* tb = (const float4*)tables;
#pragma unroll 2
    for (int t = 0; t < 32; ++t) {
#pragma unroll
        for (int r = 0; r < 8; ++r) {
            const float4 v = __ldg(&tb[(size_t)cd[t][r] * 256 + tid]);
            const float  s = sc[t][r];
            a[r].x += s * v.x; a[r].y += s * v.y;
            a[r].z += s * v.z; a[r].w += s * v.w;
        }
    }

#pragma unroll
    for (int r = 0; r < 8; ++r)
        ((float4*)out)[(size_t)(n0 + r) * 256 + tid] = a[r];
}

// ---------------------------------------------------------------------------
extern "C" void kernel_launch(void* const* d_in, const int* in_sizes, int n_in,
                              void* d_out, int out_size)
{
    const float* x      = (const float*)d_in[0];   // hidden_states
    const float* gamma  = (const float*)d_in[1];
    const float* beta   = (const float*)d_in[2];
    const float* W      = (const float*)d_in[3];   // bh4_weight
    const float* bias   = (const float*)d_in[4];   // bh4_bias
    const float* tables = (const float*)d_in[5];
    const float* obias  = (const float*)d_in[6];
    float* out = (float*)d_out;

    const int nrows = in_sizes[0] / HIDDEN;        // 8192

    const size_t smem_bytes =
        (size_t)(TILE * HSTRIDE + 32) * sizeof(float);   // ~65.8 KB
    cudaFuncSetAttribute(phase1_kernel,
                         cudaFuncAttributeMaxDynamicSharedMemorySize,
                         (int)smem_bytes);

    phase1_kernel<<<nrows / TILE, 256, smem_bytes>>>(x, gamma, beta, W, bias);
    phase2_kernel<<<nrows / 8, 256>>>(tables, obias, out);
}

// round 7
// speedup vs baseline: 1.3003x; 1.3003x over previous
#include <cuda_runtime.h>
#include <math.h>

#define HIDDEN   1024
#define NROW_MAX 8192
#define TILE     16
#define HSTRIDE  1026    // words%32==2: conflict-free pass-B; rows 8B-aligned

// scratch (static device arrays; no allocation)
__device__ int   g_code [NROW_MAX * 32];
__device__ float g_score[NROW_MAX * 32];

typedef unsigned long long ull;

__device__ __forceinline__ ull pack2(float lo, float hi) {
    ull r; asm("mov.b64 %0, {%1, %2};" : "=l"(r) : "f"(lo), "f"(hi)); return r;
}
__device__ __forceinline__ void fma2(ull& d, ull a, ull b, ull c) {
    asm("fma.rn.f32x2 %0, %1, %2, %3;" : "=l"(d) : "l"(a), "l"(b), "l"(c));
}
__device__ __forceinline__ void unpack2(ull v, float& lo, float& hi) {
    asm("mov.b64 {%0, %1}, %2;" : "=f"(lo), "=f"(hi) : "l"(v));
}
__device__ __forceinline__ void cp16(unsigned dst, const void* src) {
    asm volatile("cp.async.cg.shared.global [%0], [%1], 16;" :: "r"(dst), "l"(src));
}
__device__ __forceinline__ void cp_commit() {
    asm volatile("cp.async.commit_group;");
}
template<int N> __device__ __forceinline__ void cp_wait() {
    asm volatile("cp.async.wait_group %0;" :: "n"(N));
}

template<int N, int H>
__device__ __forceinline__ void fwht_stage(float* v) {
#pragma unroll
    for (int q = 0; q < N; q += 2 * H)
#pragma unroll
        for (int p = 0; p < H; ++p) {
            float a = v[q + p], b = v[q + H + p];
            v[q + p] = a + b; v[q + H + p] = a - b;
        }
}
__device__ __forceinline__ void fwht8(float* v) {
    fwht_stage<8,1>(v); fwht_stage<8,2>(v); fwht_stage<8,4>(v);
}
__device__ __forceinline__ void fwht32(float* v) {
    fwht_stage<32,1>(v); fwht_stage<32,2>(v); fwht_stage<32,4>(v);
    fwht_stage<32,8>(v); fwht_stage<32,16>(v);
}

// ---------------------------------------------------------------------------
// Phase 1: LN + BH4 (4 stages) + code/score.
// CTA: 16 rows, 256 threads, 2 CTAs/SM (~99 KB smem).
// W staged via cp.async, double-buffered 16 KB chunks (4 blocks each),
// prefetch one chunk ahead -> staging latency fully overlapped with compute.
// 2 warps per block: lane -> row = (w&1)*8 + (lane&7), j-quarter = lane>>3.
// FWHT pass A fused into matmul epilogue (fwht8 + 2 shfl butterflies).
// ---------------------------------------------------------------------------
extern __shared__ float smem[];

__global__ __launch_bounds__(256, 2)
void phase1_kernel(const float* __restrict__ x,
                   const float* __restrict__ gamma,
                   const float* __restrict__ beta,
                   const float* __restrict__ W,     // [4][32][32][32] = 32 chunks of 4096 floats
                   const float* __restrict__ bias)  // [320]
{
    float* sH  = smem;                     // 16 * 1026
    float* sW  = sH + TILE * HSTRIDE;      // 2 * 4096 (double buffer)
    float* sMu = sW + 2 * 4096;            // 16
    float* sRs = sMu + 16;                 // 16

    const int tid  = threadIdx.x;
    const int w    = tid >> 5;
    const int lane = tid & 31;
    const int row0 = blockIdx.x * TILE;

    const unsigned sWaddr = (unsigned)__cvta_generic_to_shared(sW);

    // prologue: prefetch chunk 0 into buffer 0 (hidden behind LayerNorm)
    {
        const float* src = W + tid * 4;
#pragma unroll
        for (int j = 0; j < 4; ++j)
            cp16(sWaddr + (tid * 4 + j * 1024) * 4, src + j * 1024);
        cp_commit();
    }

    // ---------------- LayerNorm: each warp handles 2 rows ----------------
#pragma unroll
    for (int it = 0; it < 2; ++it) {
        const int r = w * 2 + it;
        const float4* xr = (const float4*)(x + (size_t)(row0 + r) * HIDDEN);
        float4 v[8];
        float s = 0.f, ss = 0.f;
#pragma unroll
        for (int c = 0; c < 8; ++c) {
            v[c] = xr[c * 32 + lane];
            s  += v[c].x + v[c].y + v[c].z + v[c].w;
            ss += v[c].x * v[c].x + v[c].y * v[c].y + v[c].z * v[c].z + v[c].w * v[c].w;
        }
#pragma unroll
        for (int o = 16; o; o >>= 1) {
            s  += __shfl_xor_sync(0xffffffffu, s,  o);
            ss += __shfl_xor_sync(0xffffffffu, ss, o);
        }
        const float mu  = s * (1.f / 1024.f);
        const float var = ss * (1.f / 1024.f) - mu * mu;
        const float rs  = rsqrtf(var + 1e-12f);
        if (lane == 0) { sMu[r] = mu; sRs[r] = rs; }
        float* hr = sH + r * HSTRIDE;
#pragma unroll
        for (int c = 0; c < 8; ++c) {
            const int k = c * 128 + lane * 4;
            const float4 gm = ((const float4*)gamma)[c * 32 + lane];
            const float4 bt = ((const float4*)beta )[c * 32 + lane];
            hr[k + 0] = (v[c].x - mu) * rs * gm.x + bt.x;
            hr[k + 1] = (v[c].y - mu) * rs * gm.y + bt.y;
            hr[k + 2] = (v[c].z - mu) * rs * gm.z + bt.z;
            hr[k + 3] = (v[c].w - mu) * rs * gm.w + bt.w;
        }
    }

    const int lb   = w >> 1;            // local block in chunk (0..3)
    const int half = w & 1;
    const int row  = half * 8 + (lane & 7);
    const int jq   = lane >> 3;         // j-quarter 0..3

    // ---------------- 4 BH4 stages ----------------
    for (int s = 0; s < 4; ++s) {
#pragma unroll 1
        for (int c = 0; c < 8; ++c) {
            const int m = s * 8 + c;
            __syncthreads();   // compute of chunk m-1 done (and pass B / LN done)

            // prefetch chunk m+1 into the other buffer
            if (m < 31) {
                const float* src = W + (size_t)(m + 1) * 4096 + tid * 4;
                const unsigned dst = sWaddr + (((m + 1) & 1) * 4096 + tid * 4) * 4;
#pragma unroll
                for (int j = 0; j < 4; ++j)
                    cp16(dst + j * 4096, src + j * 1024);
                cp_commit();
                cp_wait<1>();           // chunk m (issued last iter) complete
            } else {
                cp_wait<0>();
            }
            __syncthreads();            // chunk m visible to all warps

            const int blk = c * 4 + lb;
            float* hrow = sH + row * HSTRIDE + blk * 32;

            float hv[32];
#pragma unroll
            for (int i = 0; i < 32; ++i) hv[i] = hrow[i];   // 4-lane broadcast

            ull acc2[4];
#pragma unroll
            for (int k = 0; k < 4; ++k) acc2[k] = 0ull;

            const float* wbase = sW + (m & 1) * 4096 + lb * 1024 + jq * 8;
#pragma unroll
            for (int i = 0; i < 32; ++i) {
                const ull hh = pack2(hv[i], hv[i]);
                const ulonglong2* wv = (const ulonglong2*)(wbase + i * 32);
                const ulonglong2 wa = wv[0];   // floats j..j+3
                const ulonglong2 wb = wv[1];   // floats j+4..j+7
                fma2(acc2[0], hh, wa.x, acc2[0]); fma2(acc2[1], hh, wa.y, acc2[1]);
                fma2(acc2[2], hh, wb.x, acc2[2]); fma2(acc2[3], hh, wb.y, acc2[3]);
            }

            // fused FWHT pass A: fwht8 in-lane, then H=8 / H=16 via shfl
            float va[8];
#pragma unroll
            for (int k = 0; k < 4; ++k) unpack2(acc2[k], va[2 * k], va[2 * k + 1]);
            fwht8(va);
#pragma unroll
            for (int k = 0; k < 8; ++k) {
                const float o = __shfl_xor_sync(0xffffffffu, va[k], 8);
                va[k] = ((jq & 1) == 0) ? (va[k] + o) : (o - va[k]);
            }
#pragma unroll
            for (int k = 0; k < 8; ++k) {
                const float o = __shfl_xor_sync(0xffffffffu, va[k], 16);
                va[k] = ((jq & 2) == 0) ? (va[k] + o) : (o - va[k]);
            }
#pragma unroll
            for (int k = 0; k < 8; ++k) hrow[jq * 8 + k] = va[k];
        }
        __syncthreads();   // all pass-A writes of this stage visible

        // FWHT pass B: across 32-blocks (stride 32), conflict-free (HSTRIDE)
#pragma unroll
        for (int g = 0; g < 2; ++g) {
            const int id = tid + g * 256;
            float* p = sH + (id & 15) * HSTRIDE + (id >> 4);
            float vv[32];
#pragma unroll
            for (int c2 = 0; c2 < 32; ++c2) vv[c2] = p[c2 * 32];
            fwht32(vv);
#pragma unroll
            for (int c2 = 0; c2 < 32; ++c2) p[c2 * 32] = vv[c2];
        }
    }
    __syncthreads();

    // ---------------- z -> code, score (xn recomputed from x, mu, rs) -------
#pragma unroll
    for (int g = 0; g < 2; ++g) {
        const int id = tid + g * 256;
        const int r  = id & 15;
        const int t  = id >> 4;
        const int n  = row0 + r;
        const float mu = sMu[r], rs = sRs[r];
        const float* xrow = x + (size_t)n * HIDDEN;
        int code = 0;
        float sc = 1.f;
#pragma unroll
        for (int j = 0; j < 10; ++j) {
            const int k = t * 10 + j;
            const float xn = (xrow[k] - mu) * rs * gamma[k] + beta[k];
            const float z  = 0.7f * sH[r * HSTRIDE + k] + 0.3f * xn + bias[k];
            if (z > 0.f) code |= (1 << j);
            sc *= 1.f / (1.f + __expf(-fabsf(z)));
        }
        g_code [n * 32 + t] = t * 1024 + code;   // pre-offset into flat table
        g_score[n * 32 + t] = sc;
    }
}

// ---------------------------------------------------------------------------
// Phase 2: out[n] = sum_t score[n,t] * tables_flat[code[n,t]] + out_bias
// 4 rows per CTA (grid = nrows/4): ~50 regs -> 4-6 CTAs/SM (occupancy back up),
// table loop OUTERMOST so concurrent CTAs sweep the same L2-resident segment.
// ---------------------------------------------------------------------------
__global__ __launch_bounds__(256)
void phase2_kernel(const float* __restrict__ tables,
                   const float* __restrict__ obias,
                   float* __restrict__ out)
{
    __shared__ float sc[32][4];
    __shared__ int   cd[32][4];
    const int n0  = blockIdx.x * 4;
    const int tid = threadIdx.x;

    if (tid < 128) {
        const int r = tid & 3;
        const int t = tid >> 2;
        sc[t][r] = g_score[(n0 + r) * 32 + t];
        cd[t][r] = g_code [(n0 + r) * 32 + t];
    }
    __syncthreads();

    const float4 ob = ((const float4*)obias)[tid];
    float4 a[4];
#pragma unroll
    for (int r = 0; r < 4; ++r) a[r] = ob;

    const float4* tb = (const float4*)tables;
#pragma unroll 2
    for (int t = 0; t < 32; ++t) {
#pragma unroll
        for (int r = 0; r < 4; ++r) {
            const float4 v = __ldg(&tb[(size_t)cd[t][r] * 256 + tid]);
            const float  s = sc[t][r];
            a[r].x += s * v.x; a[r].y += s * v.y;
            a[r].z += s * v.z; a[r].w += s * v.w;
        }
    }

#pragma unroll
    for (int r = 0; r < 4; ++r)
        ((float4*)out)[(size_t)(n0 + r) * 256 + tid] = a[r];
}

// ---------------------------------------------------------------------------
extern "C" void kernel_launch(void* const* d_in, const int* in_sizes, int n_in,
                              void* d_out, int out_size)
{
    const float* x      = (const float*)d_in[0];   // hidden_states
    const float* gamma  = (const float*)d_in[1];
    const float* beta   = (const float*)d_in[2];
    const float* W      = (const float*)d_in[3];   // bh4_weight
    const float* bias   = (const float*)d_in[4];   // bh4_bias
    const float* tables = (const float*)d_in[5];
    const float* obias  = (const float*)d_in[6];
    float* out = (float*)d_out;

    const int nrows = in_sizes[0] / HIDDEN;        // 8192

    const size_t smem_bytes =
        (size_t)(TILE * HSTRIDE + 2 * 4096 + 32) * sizeof(float);   // ~98.6 KB
    cudaFuncSetAttribute(phase1_kernel,
                         cudaFuncAttributeMaxDynamicSharedMemorySize,
                         (int)smem_bytes);

    phase1_kernel<<<nrows / TILE, 256, smem_bytes>>>(x, gamma, beta, W, bias);
    phase2_kernel<<<nrows / 4, 256>>>(tables, obias, out);
}

// round 8
// speedup vs baseline: 1.4219x; 1.0936x over previous
#include <cuda_runtime.h>
#include <math.h>

#define HIDDEN   1024
#define NROW_MAX 8192
#define TILE     16
#define HSTRIDE  1026    // words%32==2: conflict-free pass-B; rows 8B-aligned

// scratch (static device arrays; no allocation)
__device__ int   g_code [NROW_MAX * 32];
__device__ float g_score[NROW_MAX * 32];

typedef unsigned long long ull;

__device__ __forceinline__ ull pack2(float lo, float hi) {
    ull r; asm("mov.b64 %0, {%1, %2};" : "=l"(r) : "f"(lo), "f"(hi)); return r;
}
__device__ __forceinline__ void fma2(ull& d, ull a, ull b, ull c) {
    asm("fma.rn.f32x2 %0, %1, %2, %3;" : "=l"(d) : "l"(a), "l"(b), "l"(c));
}
__device__ __forceinline__ void unpack2(ull v, float& lo, float& hi) {
    asm("mov.b64 {%0, %1}, %2;" : "=f"(lo), "=f"(hi) : "l"(v));
}
__device__ __forceinline__ void cp16(unsigned dst, const void* src) {
    asm volatile("cp.async.cg.shared.global [%0], [%1], 16;" :: "r"(dst), "l"(src));
}
__device__ __forceinline__ void cp_commit() {
    asm volatile("cp.async.commit_group;");
}
template<int N> __device__ __forceinline__ void cp_wait() {
    asm volatile("cp.async.wait_group %0;" :: "n"(N));
}

template<int N, int H>
__device__ __forceinline__ void fwht_stage(float* v) {
#pragma unroll
    for (int q = 0; q < N; q += 2 * H)
#pragma unroll
        for (int p = 0; p < H; ++p) {
            float a = v[q + p], b = v[q + H + p];
            v[q + p] = a + b; v[q + H + p] = a - b;
        }
}
__device__ __forceinline__ void fwht16(float* v) {
    fwht_stage<16,1>(v); fwht_stage<16,2>(v); fwht_stage<16,4>(v); fwht_stage<16,8>(v);
}
__device__ __forceinline__ void fwht32(float* v) {
    fwht_stage<32,1>(v); fwht_stage<32,2>(v); fwht_stage<32,4>(v);
    fwht_stage<32,8>(v); fwht_stage<32,16>(v);
}

// ---------------------------------------------------------------------------
// Phase 1: LN + BH4 (4 stages) + code/score.
// CTA: 16 rows, 256 threads, 2 CTAs/SM (~98.5 KB smem).
// WARP-PRIVATE W staging: warp w owns blocks {w*4+c}. Block-diagonal structure
// means during matmul + fused FWHT pass A each warp reads/writes ONLY its own
// sH columns -> no cross-warp hazard. Each warp cp.async's its own 2 KB
// half-block chunks into a private double buffer; sync via wait_group +
// __syncwarp only. CTA barriers: 2 per stage + LN + tail = 9 (was ~70).
// Lane map per block: row = lane&15, j-half jh = lane>>4 (16 floats).
// ---------------------------------------------------------------------------
extern __shared__ float smem[];

__global__ __launch_bounds__(256, 2)
void phase1_kernel(const float* __restrict__ x,
                   const float* __restrict__ gamma,
                   const float* __restrict__ beta,
                   const float* __restrict__ W,     // [4][32][32][32]
                   const float* __restrict__ bias)  // [320]
{
    float* sH  = smem;                     // 16 * 1026
    float* sW  = sH + TILE * HSTRIDE;      // 8 warps * 1024 (2 x 512 each)
    float* sMu = sW + 8 * 1024;            // 16
    float* sRs = sMu + 16;                 // 16

    const int tid  = threadIdx.x;
    const int w    = tid >> 5;
    const int lane = tid & 31;
    const int row0 = blockIdx.x * TILE;

    const int row = lane & 15;
    const int jh  = lane >> 4;

    float* sWw = sW + w * 1024;
    const unsigned sWaddr = (unsigned)__cvta_generic_to_shared(sWw);

    // per-warp chunk m (0..31): stage s=m>>3, block c=(m>>1)&3, half h=m&1.
    // buffer parity == h (halves strictly alternate).
    auto prefetch = [&](int m) {
        const int s = m >> 3, c = (m >> 1) & 3, h = m & 1;
        const float* src = W + ((size_t)(s * 32 + w * 4 + c)) * 1024 + h * 512 + lane * 4;
        const unsigned dst = sWaddr + (unsigned)((h * 512 + lane * 4) * 4);
#pragma unroll
        for (int k = 0; k < 4; ++k)
            cp16(dst + k * 512, src + k * 128);
        cp_commit();
    };

    prefetch(0);   // hidden behind LayerNorm

    // ---------------- LayerNorm: each warp handles 2 rows ----------------
#pragma unroll
    for (int it = 0; it < 2; ++it) {
        const int r = w * 2 + it;
        const float4* xr = (const float4*)(x + (size_t)(row0 + r) * HIDDEN);
        float4 v[8];
        float s = 0.f, ss = 0.f;
#pragma unroll
        for (int c = 0; c < 8; ++c) {
            v[c] = xr[c * 32 + lane];
            s  += v[c].x + v[c].y + v[c].z + v[c].w;
            ss += v[c].x * v[c].x + v[c].y * v[c].y + v[c].z * v[c].z + v[c].w * v[c].w;
        }
#pragma unroll
        for (int o = 16; o; o >>= 1) {
            s  += __shfl_xor_sync(0xffffffffu, s,  o);
            ss += __shfl_xor_sync(0xffffffffu, ss, o);
        }
        const float mu  = s * (1.f / 1024.f);
        const float var = ss * (1.f / 1024.f) - mu * mu;
        const float rs  = rsqrtf(var + 1e-12f);
        if (lane == 0) { sMu[r] = mu; sRs[r] = rs; }
        float* hr = sH + r * HSTRIDE;
#pragma unroll
        for (int c = 0; c < 8; ++c) {
            const int k = c * 128 + lane * 4;
            const float4 gm = ((const float4*)gamma)[c * 32 + lane];
            const float4 bt = ((const float4*)beta )[c * 32 + lane];
            hr[k + 0] = (v[c].x - mu) * rs * gm.x + bt.x;
            hr[k + 1] = (v[c].y - mu) * rs * gm.y + bt.y;
            hr[k + 2] = (v[c].z - mu) * rs * gm.z + bt.z;
            hr[k + 3] = (v[c].w - mu) * rs * gm.w + bt.w;
        }
    }

    // ---------------- 4 BH4 stages (2 CTA barriers each) ----------------
    int m = 0;
    for (int s = 0; s < 4; ++s) {
        __syncthreads();   // sH ready (LN or previous pass B)

#pragma unroll
        for (int c = 0; c < 4; ++c) {
            const int blk = w * 4 + c;
            float* hrow = sH + row * HSTRIDE + blk * 32;

            ull acc2[8];
#pragma unroll
            for (int k = 0; k < 8; ++k) acc2[k] = 0ull;

#pragma unroll
            for (int h = 0; h < 2; ++h) {
                __syncwarp();                 // prior reads of this buffer done
                if (m < 31) { prefetch(m + 1); cp_wait<1>(); }
                else        { cp_wait<0>(); }
                __syncwarp();                 // chunk m visible warp-wide

                const float* wb = sWw + h * 512 + jh * 16;
                const float* hv = hrow + h * 16;
#pragma unroll
                for (int i = 0; i < 16; ++i) {
                    const float hval = hv[i];       // 2-lane LDS broadcast
                    const ull hh = pack2(hval, hval);
                    const ulonglong2* wv = (const ulonglong2*)(wb + i * 32);
                    const ulonglong2 wa = wv[0], wbq = wv[1];
                    fma2(acc2[0], hh, wa.x,  acc2[0]); fma2(acc2[1], hh, wa.y,  acc2[1]);
                    fma2(acc2[2], hh, wbq.x, acc2[2]); fma2(acc2[3], hh, wbq.y, acc2[3]);
                    const ulonglong2 wc = wv[2], wd = wv[3];
                    fma2(acc2[4], hh, wc.x, acc2[4]); fma2(acc2[5], hh, wc.y, acc2[5]);
                    fma2(acc2[6], hh, wd.x, acc2[6]); fma2(acc2[7], hh, wd.y, acc2[7]);
                }
                ++m;
            }

            // fused FWHT pass A: fwht16 on this j-half, then H=16 butterfly
            float va[16];
#pragma unroll
            for (int k = 0; k < 8; ++k) unpack2(acc2[k], va[2 * k], va[2 * k + 1]);
            fwht16(va);
#pragma unroll
            for (int k = 0; k < 16; ++k) {
                const float o = __shfl_xor_sync(0xffffffffu, va[k], 16);
                va[k] = (jh == 0) ? (va[k] + o) : (o - va[k]);
            }
#pragma unroll
            for (int k = 0; k < 16; ++k) hrow[jh * 16 + k] = va[k];
            // no barrier: this warp owns these sH columns exclusively
        }
        __syncthreads();   // all warps' pass-A writes visible

        // FWHT pass B: across 32-blocks (stride 32), conflict-free (HSTRIDE)
#pragma unroll
        for (int g = 0; g < 2; ++g) {
            const int id = tid + g * 256;
            float* p = sH + (id & 15) * HSTRIDE + (id >> 4);
            float vv[32];
#pragma unroll
            for (int c2 = 0; c2 < 32; ++c2) vv[c2] = p[c2 * 32];
            fwht32(vv);
#pragma unroll
            for (int c2 = 0; c2 < 32; ++c2) p[c2 * 32] = vv[c2];
        }
    }
    __syncthreads();

    // ---------------- z -> code, score (xn recomputed from x, mu, rs) -------
#pragma unroll
    for (int g = 0; g < 2; ++g) {
        const int id = tid + g * 256;
        const int r  = id & 15;
        const int t  = id >> 4;
        const int n  = row0 + r;
        const float mu = sMu[r], rs = sRs[r];
        const float* xrow = x + (size_t)n * HIDDEN;
        int code = 0;
        float sc = 1.f;
#pragma unroll
        for (int j = 0; j < 10; ++j) {
            const int k = t * 10 + j;
            const float xn = (xrow[k] - mu) * rs * gamma[k] + beta[k];
            const float z  = 0.7f * sH[r * HSTRIDE + k] + 0.3f * xn + bias[k];
            if (z > 0.f) code |= (1 << j);
            sc *= 1.f / (1.f + __expf(-fabsf(z)));
        }
        g_code [n * 32 + t] = t * 1024 + code;   // pre-offset into flat table
        g_score[n * 32 + t] = sc;
    }
}

// ---------------------------------------------------------------------------
// Phase 2: out[n] = sum_t score[n,t] * tables_flat[code[n,t]] + out_bias
// 4 rows per CTA, table loop OUTERMOST (L2-resident sweep). At the LTS cap
// (~12.8 TB/s logical gather) — unchanged from R7.
// ---------------------------------------------------------------------------
__global__ __launch_bounds__(256)
void phase2_kernel(const float* __restrict__ tables,
                   const float* __restrict__ obias,
                   float* __restrict__ out)
{
    __shared__ float sc[32][4];
    __shared__ int   cd[32][4];
    const int n0  = blockIdx.x * 4;
    const int tid = threadIdx.x;

    if (tid < 128) {
        const int r = tid & 3;
        const int t = tid >> 2;
        sc[t][r] = g_score[(n0 + r) * 32 + t];
        cd[t][r] = g_code [(n0 + r) * 32 + t];
    }
    __syncthreads();

    const float4 ob = ((const float4*)obias)[tid];
    float4 a[4];
#pragma unroll
    for (int r = 0; r < 4; ++r) a[r] = ob;

    const float4* tb = (const float4*)tables;
#pragma unroll 2
    for (int t = 0; t < 32; ++t) {
#pragma unroll
        for (int r = 0; r < 4; ++r) {
            const float4 v = __ldg(&tb[(size_t)cd[t][r] * 256 + tid]);
            const float  s = sc[t][r];
            a[r].x += s * v.x; a[r].y += s * v.y;
            a[r].z += s * v.z; a[r].w += s * v.w;
        }
    }

#pragma unroll
    for (int r = 0; r < 4; ++r)
        ((float4*)out)[(size_t)(n0 + r) * 256 + tid] = a[r];
}

// ---------------------------------------------------------------------------
extern "C" void kernel_launch(void* const* d_in, const int* in_sizes, int n_in,
                              void* d_out, int out_size)
{
    const float* x      = (const float*)d_in[0];   // hidden_states
    const float* gamma  = (const float*)d_in[1];
    const float* beta   = (const float*)d_in[2];
    const float* W      = (const float*)d_in[3];   // bh4_weight
    const float* bias   = (const float*)d_in[4];   // bh4_bias
    const float* tables = (const float*)d_in[5];
    const float* obias  = (const float*)d_in[6];
    float* out = (float*)d_out;

    const int nrows = in_sizes[0] / HIDDEN;        // 8192

    const size_t smem_bytes =
        (size_t)(TILE * HSTRIDE + 8 * 1024 + 32) * sizeof(float);   // ~98.5 KB
    cudaFuncSetAttribute(phase1_kernel,
                         cudaFuncAttributeMaxDynamicSharedMemorySize,
                         (int)smem_bytes);

    phase1_kernel<<<nrows / TILE, 256, smem_bytes>>>(x, gamma, beta, W, bias);
    phase2_kernel<<<nrows / 4, 256>>>(tables, obias, out);
}